// round 11
// baseline (speedup 1.0000x reference)
#include <cuda_runtime.h>
#include <cstdint>

#define D      128
#define D4     32
#define KC     1024
#define MLVL   4
#define TM     128         // rows per block
#define TKC    64          // codes per chunk
#define NCH    (KC / TKC)  // 16
#define NTHR   128
#define RST    132         // padded row stride (floats)

__device__ float              g_e2[MLVL * KC];
__device__ unsigned long long g_lsum  = 0ULL;
__device__ unsigned int       g_count = 0u;

// smem layout (float offsets)
#define OFF_CS   (TM * RST)                 // 16896
#define OFF_E2   (OFF_CS + TKC * RST)       // 25344
#define OFF_R2S  (OFF_E2 + KC)              // 26368
#define OFF_IDX  (OFF_R2S + TM)             // 26496
#define SMEM_FLOATS (OFF_IDX + MLVL * TM)   // 27008
#define SMEM_BYTES  (SMEM_FLOATS * 4)       // 108032

#define LSCALE 17179869184.0                // 2^34

__device__ __forceinline__ void fma2(unsigned long long& acc,
                                     unsigned long long a,
                                     unsigned long long b) {
    asm("fma.rn.f32x2 %0, %1, %2, %3;" : "=l"(acc) : "l"(a), "l"(b), "l"(acc));
}
__device__ __forceinline__ void unpack2(unsigned long long v, float& lo, float& hi) {
    asm("mov.b64 {%0, %1}, %2;" : "=f"(lo), "=f"(hi) : "l"(v));
}
__device__ __forceinline__ void cp_async16(void* smem_dst, const void* gsrc) {
    unsigned saddr = (unsigned)__cvta_generic_to_shared(smem_dst);
    asm volatile("cp.async.ca.shared.global [%0], [%1], 16;" :: "r"(saddr), "l"(gsrc));
}

// ---- e2[k] = sum_d cb[k][d]^2, warp per code, coalesced ----
__global__ void e2_kernel(const float* __restrict__ cb) {
    int code = blockIdx.x * 4 + (threadIdx.x >> 5);
    int l = threadIdx.x & 31;
    const float4* row = (const float4*)(cb + (size_t)code * D);
    float4 v = row[l];
    float p = __fmaf_rn(v.x, v.x, 0.f);
    p = __fmaf_rn(v.y, v.y, p);
    p = __fmaf_rn(v.z, v.z, p);
    p = __fmaf_rn(v.w, v.w, p);
#pragma unroll
    for (int off = 16; off >= 1; off >>= 1)
        p = __fadd_rn(p, __shfl_xor_sync(0xffffffffu, p, off));
    if (l == 0) g_e2[code] = p;
}

// one pipelined q-step: consumes RV, prefetches RVN (next q); cv double-buffered
// (cvA used now, cvB one ahead, cvN_ two ahead) -> LDS->use distance ~32 FFMA2
#define QSTEP(QI, RV, RVN)                                              \
    {                                                                   \
        const int qn_ = ((QI) + 1) & (D4 - 1);                          \
        _Pragma("unroll")                                               \
        for (int j = 0; j < 8; j++) {                                   \
            ulonglong2 cvN_ = (j < 6) ? cvp[264 * (j + 2) + (QI)]       \
                                      : cvp[264 * (j - 6) + qn_];       \
            (RVN)[j] = rvp[528 * j + qn_];                              \
            _Pragma("unroll")                                           \
            for (int i = 0; i < 8; i++) {                               \
                fma2(acc[i][j], (RV)[i].x, cvA.x);                      \
                fma2(acc[i][j], (RV)[i].y, cvA.y);                      \
            }                                                           \
            cvA = cvB; cvB = cvN_;                                      \
        }                                                               \
    }

__global__ __launch_bounds__(NTHR, 2)
void rvq_kernel(const float* __restrict__ x, const float* __restrict__ cb,
                float* __restrict__ y, float* __restrict__ loss_out,
                int nrows, long long nelems) {
    extern __shared__ float smem[];
    float* rs    = smem;                    // [TM][RST]
    float* cs    = smem + OFF_CS;           // [TKC][RST]
    float* e2all = smem + OFF_E2;           // [KC]
    float* r2s   = smem + OFF_R2S;          // [TM]
    int*   idxs  = (int*)(smem + OFF_IDX);  // [MLVL][TM]

    const int t    = threadIdx.x;
    const int w    = t >> 5;
    const int l    = t & 31;
    const int rowg = t >> 3;               // 0..15 -> rows rowg + 16*i (i=0..7)
    const int txc  = t & 7;                // 0..7  -> codes txc + 8*j (j=0..7)

    const int rowBase = blockIdx.x * TM;
    if (rowBase >= nrows) return;
    const float4* x4  = (const float4*)(x + (size_t)rowBase * D);
    const float4* cb4 = (const float4*)cb;

    double lsum = 0.0;

    // ---- kick off staging of chunk (lvl=0, c=0) right away ----
    {
#pragma unroll
        for (int ii = 0; ii < 16; ii++) {
            int e = t + NTHR * ii;
            int k = e >> 5, qq = e & 31;
            cp_async16(&cs[k * RST + 4 * qq], cb4 + e);
        }
        asm volatile("cp.async.commit_group;");
    }

    // ---- initial residual load + r2 (overlaps the copy above) ----
#pragma unroll
    for (int i2 = 0; i2 < 32; i2++) {
        int row = w + 4 * i2;
        float4 v = x4[(size_t)row * D4 + l];
        *(float4*)&rs[row * RST + 4 * l] = v;
        float p = __fmaf_rn(v.x, v.x, 0.f);
        p = __fmaf_rn(v.y, v.y, p);
        p = __fmaf_rn(v.z, v.z, p);
        p = __fmaf_rn(v.w, v.w, p);
#pragma unroll
        for (int off = 16; off >= 1; off >>= 1)
            p = __fadd_rn(p, __shfl_xor_sync(0xffffffffu, p, off));
        if (l == 0) r2s[row] = p;
    }

    const ulonglong2* rvp = (const ulonglong2*)&rs[rowg * RST];   // rows: +528*i
    const ulonglong2* cvp = (const ulonglong2*)&cs[txc * RST];    // codes: +264*j

    for (int lvl = 0; lvl < MLVL; lvl++) {
        const float4* cbl4 = cb4 + (size_t)lvl * KC * D4;

        // stage this level's e2 (read after the chunk-0 barrier below)
        {
            const float4* e2src = (const float4*)(g_e2 + lvl * KC);
            float4 a = e2src[t];
            float4 b = e2src[t + NTHR];
            *(float4*)&e2all[4 * t] = a;
            *(float4*)&e2all[4 * (t + NTHR)] = b;
        }

        float r2r[8];
#pragma unroll
        for (int i = 0; i < 8; i++) r2r[i] = r2s[rowg + 16 * i];

        float bd[8]; int bi[8];
#pragma unroll
        for (int i = 0; i < 8; i++) { bd[i] = 3.4e38f; bi[i] = 0; }

        for (int c = 0; c < NCH; c++) {
            // cs for this chunk was staged earlier; make it visible
            asm volatile("cp.async.wait_group 0;");
            __syncthreads();

            // ---- 8x8 tile, software-pipelined (cv 2-deep, rv ping-pong) ----
            unsigned long long acc[8][8];
#pragma unroll
            for (int i = 0; i < 8; i++)
#pragma unroll
                for (int j = 0; j < 8; j++) acc[i][j] = 0ull;

            ulonglong2 rvA[8], rvB[8];
#pragma unroll
            for (int i = 0; i < 8; i++) rvA[i] = rvp[528 * i];
            ulonglong2 cvA = cvp[0];
            ulonglong2 cvB = cvp[264];

            for (int qq = 0; qq < D4; qq += 2) {
                QSTEP(qq,     rvA, rvB)
                QSTEP(qq + 1, rvB, rvA)
            }

            __syncthreads();   // all warps done reading cs

            // ---- issue next chunk's copy NOW; completes under the epilogue ----
            {
                const float4* nsrc = 0;
                if (c + 1 < NCH)         nsrc = cbl4 + (size_t)(c + 1) * TKC * D4;
                else if (lvl + 1 < MLVL) nsrc = cb4 + (size_t)(lvl + 1) * KC * D4;
                if (nsrc) {
#pragma unroll
                    for (int ii = 0; ii < 16; ii++) {
                        int e = t + NTHR * ii;
                        int k = e >> 5, qq2 = e & 31;
                        cp_async16(&cs[k * RST + 4 * qq2], nsrc + e);
                    }
                    asm volatile("cp.async.commit_group;");
                }
            }

            // ---- distances + running argmin (ascending k, strict <) ----
#pragma unroll
            for (int j = 0; j < 8; j++) {
                int kk = txc + 8 * j;
                float e2k = e2all[c * TKC + kk];
                int kg = c * TKC + kk;
#pragma unroll
                for (int i = 0; i < 8; i++) {
                    float lo, hi;
                    unpack2(acc[i][j], lo, hi);
                    float dot = __fadd_rn(lo, hi);
                    float s = __fadd_rn(r2r[i], e2k);
                    float dv = __fmaf_rn(-2.0f, dot, s);
                    if (dv < bd[i]) { bd[i] = dv; bi[i] = kg; }
                }
            }
        }

        // ---- argmin across the 8 txc lanes (first-min via index tiebreak) ----
#pragma unroll
        for (int off = 1; off <= 4; off <<= 1)
#pragma unroll
            for (int i = 0; i < 8; i++) {
                float od = __shfl_xor_sync(0xffffffffu, bd[i], off);
                int   oi = __shfl_xor_sync(0xffffffffu, bi[i], off);
                if (od < bd[i] || (od == bd[i] && oi < bi[i])) { bd[i] = od; bi[i] = oi; }
            }
        if (txc == 0)
#pragma unroll
            for (int i = 0; i < 8; i++)
                idxs[lvl * TM + rowg + 16 * i] = bi[i];
        __syncthreads();

        // ---- residual update + r2 + loss partial ----
#pragma unroll
        for (int i2 = 0; i2 < 32; i2++) {
            int row = w + 4 * i2;
            int qi = idxs[lvl * TM + row];
            float4 qv = cbl4[(size_t)qi * D4 + l];
            float* rp = &rs[row * RST + 4 * l];
            float4 rv = *(float4*)rp;
            rv.x = __fsub_rn(rv.x, qv.x);
            rv.y = __fsub_rn(rv.y, qv.y);
            rv.z = __fsub_rn(rv.z, qv.z);
            rv.w = __fsub_rn(rv.w, qv.w);
            *(float4*)rp = rv;
            float p = __fmaf_rn(rv.x, rv.x, 0.f);
            p = __fmaf_rn(rv.y, rv.y, p);
            p = __fmaf_rn(rv.z, rv.z, p);
            p = __fmaf_rn(rv.w, rv.w, p);
            lsum += (double)p;               // (q - r_pre)^2 == r_post^2
#pragma unroll
            for (int off = 16; off >= 1; off >>= 1)
                p = __fadd_rn(p, __shfl_xor_sync(0xffffffffu, p, off));
            if (l == 0) r2s[row] = p;
        }
        __syncthreads();
    }

    // ---- y = x + (q_sum - x), reference rounding chain ----
    {
        float4* y4 = (float4*)(y + (size_t)rowBase * D);
#pragma unroll
        for (int i2 = 0; i2 < 32; i2++) {
            int row = w + 4 * i2;
            int a0 = idxs[0 * TM + row], a1 = idxs[1 * TM + row];
            int a2 = idxs[2 * TM + row], a3 = idxs[3 * TM + row];
            float4 q0 = cb4[((size_t)0 * KC + a0) * D4 + l];
            float4 q1 = cb4[((size_t)1 * KC + a1) * D4 + l];
            float4 q2 = cb4[((size_t)2 * KC + a2) * D4 + l];
            float4 q3 = cb4[((size_t)3 * KC + a3) * D4 + l];
            float4 xv = x4[(size_t)row * D4 + l];
            float4 o;
            o.x = __fadd_rn(xv.x, __fsub_rn(__fadd_rn(__fadd_rn(__fadd_rn(q0.x, q1.x), q2.x), q3.x), xv.x));
            o.y = __fadd_rn(xv.y, __fsub_rn(__fadd_rn(__fadd_rn(__fadd_rn(q0.y, q1.y), q2.y), q3.y), xv.y));
            o.z = __fadd_rn(xv.z, __fsub_rn(__fadd_rn(__fadd_rn(__fadd_rn(q0.z, q1.z), q2.z), q3.z), xv.z));
            o.w = __fadd_rn(xv.w, __fsub_rn(__fadd_rn(__fadd_rn(__fadd_rn(q0.w, q1.w), q2.w), q3.w), xv.w));
            y4[(size_t)row * D4 + l] = o;
        }
    }

    // ---- deterministic fixed-point loss reduction (int64, replay-safe) ----
    {
        long long lv = (long long)(lsum * LSCALE);
#pragma unroll
        for (int off = 16; off >= 1; off >>= 1)
            lv += __shfl_xor_sync(0xffffffffu, lv, off);
        if (l == 0) atomicAdd(&g_lsum, (unsigned long long)lv);
        __syncthreads();
        if (t == 0) {
            __threadfence();
            unsigned int prev = atomicAdd(&g_count, 1u);
            if (prev == gridDim.x - 1) {
                unsigned long long s = atomicExch(&g_lsum, 0ULL);
                loss_out[0] = (float)(1.25 * ((double)(long long)s / LSCALE)
                                           / (double)nelems);
                atomicExch(&g_count, 0u);
            }
        }
    }
}

extern "C" void kernel_launch(void* const* d_in, const int* in_sizes, int n_in,
                              void* d_out, int out_size) {
    const float* x  = (const float*)d_in[0];
    const float* cb = (const float*)d_in[1];
    float* y = (float*)d_out;

    const long long xelems = (long long)in_sizes[0];
    const int nrows   = (int)(xelems / D);
    const int nblocks = (nrows + TM - 1) / TM;
    float* loss_out = y + xelems;

    cudaFuncSetAttribute(rvq_kernel, cudaFuncAttributeMaxDynamicSharedMemorySize, SMEM_BYTES);

    e2_kernel<<<MLVL * KC / 4, 128>>>(cb);
    rvq_kernel<<<nblocks, NTHR, SMEM_BYTES>>>(x, cb, y, loss_out, nrows, xelems);
}

// round 14
// speedup vs baseline: 1.9199x; 1.9199x over previous
#include <cuda_runtime.h>
#include <cstdint>

#define D      128
#define D4     32
#define KC     1024
#define MLVL   4
#define TM     112         // rows per block: 293 CTAs -> balanced single wave
#define NR     7           // rows per thread
#define TKC    64          // codes per chunk
#define NCH    (KC / TKC)  // 16
#define NTHR   128
#define RST    132         // padded row stride (floats)

__device__ float              g_e2[MLVL * KC];
__device__ unsigned long long g_lsum  = 0ULL;
__device__ unsigned int       g_count = 0u;

// smem layout (float offsets)
#define OFF_CS   (TM * RST)                 // 14784
#define OFF_E2   (OFF_CS + TKC * RST)       // 23232
#define OFF_R2S  (OFF_E2 + KC)              // 24256
#define OFF_IDX  (OFF_R2S + TM)             // 24368
#define SMEM_FLOATS (OFF_IDX + MLVL * TM)   // 24816
#define SMEM_BYTES  (SMEM_FLOATS * 4)       // 99264

#define LSCALE 17179869184.0                // 2^34

__device__ __forceinline__ void fma2(unsigned long long& acc,
                                     unsigned long long a,
                                     unsigned long long b) {
    asm("fma.rn.f32x2 %0, %1, %2, %3;" : "=l"(acc) : "l"(a), "l"(b), "l"(acc));
}
__device__ __forceinline__ void unpack2(unsigned long long v, float& lo, float& hi) {
    asm("mov.b64 {%0, %1}, %2;" : "=f"(lo), "=f"(hi) : "l"(v));
}
__device__ __forceinline__ void cp_async16(void* smem_dst, const void* gsrc) {
    unsigned saddr = (unsigned)__cvta_generic_to_shared(smem_dst);
    asm volatile("cp.async.ca.shared.global [%0], [%1], 16;" :: "r"(saddr), "l"(gsrc));
}

// ---- e2[k] = sum_d cb[k][d]^2, warp per code, coalesced ----
__global__ void e2_kernel(const float* __restrict__ cb) {
    int code = blockIdx.x * 4 + (threadIdx.x >> 5);
    int l = threadIdx.x & 31;
    const float4* row = (const float4*)(cb + (size_t)code * D);
    float4 v = row[l];
    float p = __fmaf_rn(v.x, v.x, 0.f);
    p = __fmaf_rn(v.y, v.y, p);
    p = __fmaf_rn(v.z, v.z, p);
    p = __fmaf_rn(v.w, v.w, p);
#pragma unroll
    for (int off = 16; off >= 1; off >>= 1)
        p = __fadd_rn(p, __shfl_xor_sync(0xffffffffu, p, off));
    if (l == 0) g_e2[code] = p;
}

// one pipelined q-step (R9 structure): consumes RV, prefetches RVN for next q
// (statically pruned to j<NR), cv carried one j ahead.
#define QSTEP(QI, RV, RVN)                                              \
    {                                                                   \
        const int qn_ = ((QI) + 1) & (D4 - 1);                          \
        _Pragma("unroll")                                               \
        for (int j = 0; j < 8; j++) {                                   \
            ulonglong2 cvN_ = (j < 7) ? cvp[264 * (j + 1) + (QI)]       \
                                      : cvp[qn_];                       \
            if (j < NR) (RVN)[j] = rvp[528 * j + qn_];                  \
            _Pragma("unroll")                                           \
            for (int i = 0; i < NR; i++) {                              \
                fma2(acc[i][j], (RV)[i].x, cv.x);                       \
                fma2(acc[i][j], (RV)[i].y, cv.y);                       \
            }                                                           \
            cv = cvN_;                                                  \
        }                                                               \
    }

__global__ __launch_bounds__(NTHR, 2)
void rvq_kernel(const float* __restrict__ x, const float* __restrict__ cb,
                float* __restrict__ y, float* __restrict__ loss_out,
                int nrows, long long nelems) {
    extern __shared__ float smem[];
    float* rs    = smem;                    // [TM][RST]
    float* cs    = smem + OFF_CS;           // [TKC][RST]
    float* e2all = smem + OFF_E2;           // [KC]
    float* r2s   = smem + OFF_R2S;          // [TM]
    int*   idxs  = (int*)(smem + OFF_IDX);  // [MLVL][TM]

    const int t    = threadIdx.x;
    const int w    = t >> 5;
    const int l    = t & 31;
    const int rowg = t >> 3;               // 0..15 -> rows rowg + 16*i (i=0..NR-1)
    const int txc  = t & 7;                // 0..7  -> codes txc + 8*j (j=0..7)

    const int rowBase = blockIdx.x * TM;
    if (rowBase >= nrows) return;
    const int rowLim = (nrows - rowBase < TM) ? (nrows - rowBase) : TM;
    const float4* x4  = (const float4*)(x + (size_t)rowBase * D);
    const float4* cb4 = (const float4*)cb;

    double lsum = 0.0;

    // ---- kick off staging of chunk (lvl=0, c=0) right away ----
    {
#pragma unroll
        for (int ii = 0; ii < 16; ii++) {
            int e = t + NTHR * ii;
            int k = e >> 5, qq = e & 31;
            cp_async16(&cs[k * RST + 4 * qq], cb4 + e);
        }
        asm volatile("cp.async.commit_group;");
    }

    // ---- initial residual load + r2 (zero-fill rows beyond rowLim) ----
#pragma unroll
    for (int i2 = 0; i2 < TM / 4; i2++) {
        int row = w + 4 * i2;
        float4 v = make_float4(0.f, 0.f, 0.f, 0.f);
        if (row < rowLim) v = x4[(size_t)row * D4 + l];
        *(float4*)&rs[row * RST + 4 * l] = v;
        float p = __fmaf_rn(v.x, v.x, 0.f);
        p = __fmaf_rn(v.y, v.y, p);
        p = __fmaf_rn(v.z, v.z, p);
        p = __fmaf_rn(v.w, v.w, p);
#pragma unroll
        for (int off = 16; off >= 1; off >>= 1)
            p = __fadd_rn(p, __shfl_xor_sync(0xffffffffu, p, off));
        if (l == 0) r2s[row] = p;
    }
    // CRITICAL: order all warps' r2s/rs prologue writes before any cross-warp
    // read (the lvl-0 r2r reads below). R9's missing barrier here was a latent
    // race: fl(r2+e2k) rounding is k-dependent, so stale r2 flips argmins.
    __syncthreads();

    const ulonglong2* rvp = (const ulonglong2*)&rs[rowg * RST];   // rows: +528*i
    const ulonglong2* cvp = (const ulonglong2*)&cs[txc * RST];    // codes: +264*j

    for (int lvl = 0; lvl < MLVL; lvl++) {
        const float4* cbl4 = cb4 + (size_t)lvl * KC * D4;

        // stage this level's e2 (read after the chunk-0 barrier below)
        {
            const float4* e2src = (const float4*)(g_e2 + lvl * KC);
            float4 a = e2src[t];
            float4 b = e2src[t + NTHR];
            *(float4*)&e2all[4 * t] = a;
            *(float4*)&e2all[4 * (t + NTHR)] = b;
        }

        float r2r[NR];
#pragma unroll
        for (int i = 0; i < NR; i++) r2r[i] = r2s[rowg + 16 * i];

        float bd[NR]; int bi[NR];
#pragma unroll
        for (int i = 0; i < NR; i++) { bd[i] = 3.4e38f; bi[i] = 0; }

        for (int c = 0; c < NCH; c++) {
            // cs for this chunk was staged earlier; make it visible
            asm volatile("cp.async.wait_group 0;");
            __syncthreads();

            // ---- NRx8 tile, software-pipelined (cv 1-j ahead, rv ping-pong) ----
            unsigned long long acc[NR][8];
#pragma unroll
            for (int i = 0; i < NR; i++)
#pragma unroll
                for (int j = 0; j < 8; j++) acc[i][j] = 0ull;

            ulonglong2 rvA[NR], rvB[NR];
#pragma unroll
            for (int i = 0; i < NR; i++) rvA[i] = rvp[528 * i];
            ulonglong2 cv = cvp[0];

            for (int qq = 0; qq < D4; qq += 2) {
                QSTEP(qq,     rvA, rvB)
                QSTEP(qq + 1, rvB, rvA)
            }

            __syncthreads();   // all warps done reading cs

            // ---- issue next chunk's copy NOW; completes under the epilogue ----
            {
                const float4* nsrc = 0;
                if (c + 1 < NCH)         nsrc = cbl4 + (size_t)(c + 1) * TKC * D4;
                else if (lvl + 1 < MLVL) nsrc = cb4 + (size_t)(lvl + 1) * KC * D4;
                if (nsrc) {
#pragma unroll
                    for (int ii = 0; ii < 16; ii++) {
                        int e = t + NTHR * ii;
                        int k = e >> 5, qq2 = e & 31;
                        cp_async16(&cs[k * RST + 4 * qq2], nsrc + e);
                    }
                    asm volatile("cp.async.commit_group;");
                }
            }

            // ---- distances + running argmin (ascending k, strict <) ----
#pragma unroll
            for (int j = 0; j < 8; j++) {
                int kk = txc + 8 * j;
                float e2k = e2all[c * TKC + kk];
                int kg = c * TKC + kk;
#pragma unroll
                for (int i = 0; i < NR; i++) {
                    float lo, hi;
                    unpack2(acc[i][j], lo, hi);
                    float dot = __fadd_rn(lo, hi);
                    float s = __fadd_rn(r2r[i], e2k);
                    float dv = __fmaf_rn(-2.0f, dot, s);
                    if (dv < bd[i]) { bd[i] = dv; bi[i] = kg; }
                }
            }
        }

        // ---- argmin across the 8 txc lanes (first-min via index tiebreak) ----
#pragma unroll
        for (int off = 1; off <= 4; off <<= 1)
#pragma unroll
            for (int i = 0; i < NR; i++) {
                float od = __shfl_xor_sync(0xffffffffu, bd[i], off);
                int   oi = __shfl_xor_sync(0xffffffffu, bi[i], off);
                if (od < bd[i] || (od == bd[i] && oi < bi[i])) { bd[i] = od; bi[i] = oi; }
            }
        if (txc == 0)
#pragma unroll
            for (int i = 0; i < NR; i++)
                idxs[lvl * TM + rowg + 16 * i] = bi[i];
        __syncthreads();

        // ---- residual update + r2 + loss partial (loss guarded by rowLim) ----
#pragma unroll
        for (int i2 = 0; i2 < TM / 4; i2++) {
            int row = w + 4 * i2;
            int qi = idxs[lvl * TM + row];
            float4 qv = cbl4[(size_t)qi * D4 + l];
            float* rp = &rs[row * RST + 4 * l];
            float4 rv = *(float4*)rp;
            rv.x = __fsub_rn(rv.x, qv.x);
            rv.y = __fsub_rn(rv.y, qv.y);
            rv.z = __fsub_rn(rv.z, qv.z);
            rv.w = __fsub_rn(rv.w, qv.w);
            *(float4*)rp = rv;
            float p = __fmaf_rn(rv.x, rv.x, 0.f);
            p = __fmaf_rn(rv.y, rv.y, p);
            p = __fmaf_rn(rv.z, rv.z, p);
            p = __fmaf_rn(rv.w, rv.w, p);
            if (row < rowLim) lsum += (double)p;   // (q - r_pre)^2 == r_post^2
#pragma unroll
            for (int off = 16; off >= 1; off >>= 1)
                p = __fadd_rn(p, __shfl_xor_sync(0xffffffffu, p, off));
            if (l == 0) r2s[row] = p;
        }
        __syncthreads();
    }

    // ---- y = x + (q_sum - x), reference rounding chain (guarded) ----
    {
        float4* y4 = (float4*)(y + (size_t)rowBase * D);
#pragma unroll
        for (int i2 = 0; i2 < TM / 4; i2++) {
            int row = w + 4 * i2;
            if (row < rowLim) {
                int a0 = idxs[0 * TM + row], a1 = idxs[1 * TM + row];
                int a2 = idxs[2 * TM + row], a3 = idxs[3 * TM + row];
                float4 q0 = cb4[((size_t)0 * KC + a0) * D4 + l];
                float4 q1 = cb4[((size_t)1 * KC + a1) * D4 + l];
                float4 q2 = cb4[((size_t)2 * KC + a2) * D4 + l];
                float4 q3 = cb4[((size_t)3 * KC + a3) * D4 + l];
                float4 xv = x4[(size_t)row * D4 + l];
                float4 o;
                o.x = __fadd_rn(xv.x, __fsub_rn(__fadd_rn(__fadd_rn(__fadd_rn(q0.x, q1.x), q2.x), q3.x), xv.x));
                o.y = __fadd_rn(xv.y, __fsub_rn(__fadd_rn(__fadd_rn(__fadd_rn(q0.y, q1.y), q2.y), q3.y), xv.y));
                o.z = __fadd_rn(xv.z, __fsub_rn(__fadd_rn(__fadd_rn(__fadd_rn(q0.z, q1.z), q2.z), q3.z), xv.z));
                o.w = __fadd_rn(xv.w, __fsub_rn(__fadd_rn(__fadd_rn(__fadd_rn(q0.w, q1.w), q2.w), q3.w), xv.w));
                y4[(size_t)row * D4 + l] = o;
            }
        }
    }

    // ---- deterministic fixed-point loss reduction (int64, replay-safe) ----
    {
        long long lv = (long long)(lsum * LSCALE);
#pragma unroll
        for (int off = 16; off >= 1; off >>= 1)
            lv += __shfl_xor_sync(0xffffffffu, lv, off);
        if (l == 0) atomicAdd(&g_lsum, (unsigned long long)lv);
        __syncthreads();
        if (t == 0) {
            __threadfence();
            unsigned int prev = atomicAdd(&g_count, 1u);
            if (prev == gridDim.x - 1) {
                unsigned long long s = atomicExch(&g_lsum, 0ULL);
                loss_out[0] = (float)(1.25 * ((double)(long long)s / LSCALE)
                                           / (double)nelems);
                atomicExch(&g_count, 0u);
            }
        }
    }
}

extern "C" void kernel_launch(void* const* d_in, const int* in_sizes, int n_in,
                              void* d_out, int out_size) {
    const float* x  = (const float*)d_in[0];
    const float* cb = (const float*)d_in[1];
    float* y = (float*)d_out;

    const long long xelems = (long long)in_sizes[0];
    const int nrows   = (int)(xelems / D);
    const int nblocks = (nrows + TM - 1) / TM;
    float* loss_out = y + xelems;

    cudaFuncSetAttribute(rvq_kernel, cudaFuncAttributeMaxDynamicSharedMemorySize, SMEM_BYTES);

    e2_kernel<<<MLVL * KC / 4, 128>>>(cb);
    rvq_kernel<<<nblocks, NTHR, SMEM_BYTES>>>(x, cb, y, loss_out, nrows, xelems);
}

// round 15
// speedup vs baseline: 2.1023x; 1.0950x over previous
#include <cuda_runtime.h>
#include <cstdint>

#define D      128
#define D4     32
#define KC     1024
#define MLVL   4
#define TM     112         // rows per block: 293 CTAs -> balanced single wave
#define NR     7           // rows per thread
#define TKC    64          // codes per chunk
#define NCH    (KC / TKC)  // 16
#define NTHR   128
#define RST    132         // padded row stride (floats)

__device__ float              g_e2[MLVL * KC];
__device__ unsigned long long g_lsum  = 0ULL;
__device__ unsigned int       g_count = 0u;

// smem layout (float offsets)
#define OFF_CS   (TM * RST)                 // 14784
#define OFF_E2   (OFF_CS + TKC * RST)       // 23232
#define OFF_R2S  (OFF_E2 + KC)              // 24256
#define OFF_IDX  (OFF_R2S + TM)             // 24368
#define SMEM_FLOATS (OFF_IDX + MLVL * TM)   // 24816
#define SMEM_BYTES  (SMEM_FLOATS * 4)       // 99264

#define LSCALE 17179869184.0                // 2^34

__device__ __forceinline__ void fma2(unsigned long long& acc,
                                     unsigned long long a,
                                     unsigned long long b) {
    asm("fma.rn.f32x2 %0, %1, %2, %3;" : "=l"(acc) : "l"(a), "l"(b), "l"(acc));
}
__device__ __forceinline__ void unpack2(unsigned long long v, float& lo, float& hi) {
    asm("mov.b64 {%0, %1}, %2;" : "=f"(lo), "=f"(hi) : "l"(v));
}
__device__ __forceinline__ void cp_async16(void* smem_dst, const void* gsrc) {
    unsigned saddr = (unsigned)__cvta_generic_to_shared(smem_dst);
    asm volatile("cp.async.ca.shared.global [%0], [%1], 16;" :: "r"(saddr), "l"(gsrc));
}

// ---- e2[k] = sum_d cb[k][d]^2, warp per code, coalesced ----
__global__ void e2_kernel(const float* __restrict__ cb) {
    int code = blockIdx.x * 4 + (threadIdx.x >> 5);
    int l = threadIdx.x & 31;
    const float4* row = (const float4*)(cb + (size_t)code * D);
    float4 v = row[l];
    float p = __fmaf_rn(v.x, v.x, 0.f);
    p = __fmaf_rn(v.y, v.y, p);
    p = __fmaf_rn(v.z, v.z, p);
    p = __fmaf_rn(v.w, v.w, p);
#pragma unroll
    for (int off = 16; off >= 1; off >>= 1)
        p = __fadd_rn(p, __shfl_xor_sync(0xffffffffu, p, off));
    if (l == 0) g_e2[code] = p;
}

// one pipelined q-step: rv ping-pong across q, cv ping-pong across j (by
// parity, compile-time refs -> no MOVs), x-pass then y-pass per j so each
// acc's two FMAs sit >= 7 instructions apart (kills the 4-cyc RAW stall).
// Per-acc accumulation order (x then y, q ascending) is unchanged -> bitwise
// identical dots.
#define QSTEP(QI, RV, RVN)                                              \
    {                                                                   \
        const int qn_ = ((QI) + 1) & (D4 - 1);                          \
        _Pragma("unroll")                                               \
        for (int j = 0; j < 8; j++) {                                   \
            ulonglong2& cvC = (j & 1) ? cvB : cvA;                      \
            ulonglong2& cvP = (j & 1) ? cvA : cvB;                      \
            cvP = (j < 7) ? cvp[264 * (j + 1) + (QI)] : cvp[qn_];       \
            if (j < NR) (RVN)[j] = rvp[528 * j + qn_];                  \
            _Pragma("unroll")                                           \
            for (int i = 0; i < NR; i++)                                \
                fma2(acc[i][j], (RV)[i].x, cvC.x);                      \
            _Pragma("unroll")                                           \
            for (int i = 0; i < NR; i++)                                \
                fma2(acc[i][j], (RV)[i].y, cvC.y);                      \
        }                                                               \
    }

__global__ __launch_bounds__(NTHR, 2)
void rvq_kernel(const float* __restrict__ x, const float* __restrict__ cb,
                float* __restrict__ y, float* __restrict__ loss_out,
                int nrows, long long nelems) {
    extern __shared__ float smem[];
    float* rs    = smem;                    // [TM][RST]
    float* cs    = smem + OFF_CS;           // [TKC][RST]
    float* e2all = smem + OFF_E2;           // [KC]
    float* r2s   = smem + OFF_R2S;          // [TM]
    int*   idxs  = (int*)(smem + OFF_IDX);  // [MLVL][TM]

    const int t    = threadIdx.x;
    const int w    = t >> 5;
    const int l    = t & 31;
    const int rowg = t >> 3;               // 0..15 -> rows rowg + 16*i (i=0..NR-1)
    const int txc  = t & 7;                // 0..7  -> codes txc + 8*j (j=0..7)

    const int rowBase = blockIdx.x * TM;
    if (rowBase >= nrows) return;
    const int rowLim = (nrows - rowBase < TM) ? (nrows - rowBase) : TM;
    const float4* x4  = (const float4*)(x + (size_t)rowBase * D);
    const float4* cb4 = (const float4*)cb;

    double lsum = 0.0;

    // ---- kick off staging of chunk (lvl=0, c=0) right away ----
    {
#pragma unroll
        for (int ii = 0; ii < 16; ii++) {
            int e = t + NTHR * ii;
            int k = e >> 5, qq = e & 31;
            cp_async16(&cs[k * RST + 4 * qq], cb4 + e);
        }
        asm volatile("cp.async.commit_group;");
    }

    // ---- initial residual load + r2 (zero-fill rows beyond rowLim) ----
#pragma unroll
    for (int i2 = 0; i2 < TM / 4; i2++) {
        int row = w + 4 * i2;
        float4 v = make_float4(0.f, 0.f, 0.f, 0.f);
        if (row < rowLim) v = x4[(size_t)row * D4 + l];
        *(float4*)&rs[row * RST + 4 * l] = v;
        float p = __fmaf_rn(v.x, v.x, 0.f);
        p = __fmaf_rn(v.y, v.y, p);
        p = __fmaf_rn(v.z, v.z, p);
        p = __fmaf_rn(v.w, v.w, p);
#pragma unroll
        for (int off = 16; off >= 1; off >>= 1)
            p = __fadd_rn(p, __shfl_xor_sync(0xffffffffu, p, off));
        if (l == 0) r2s[row] = p;
    }
    // Order all warps' r2s/rs prologue writes before any cross-warp read:
    // fl(r2+e2k) rounding is k-dependent, so stale r2 flips argmins.
    __syncthreads();

    const ulonglong2* rvp = (const ulonglong2*)&rs[rowg * RST];   // rows: +528*i
    const ulonglong2* cvp = (const ulonglong2*)&cs[txc * RST];    // codes: +264*j

    for (int lvl = 0; lvl < MLVL; lvl++) {
        const float4* cbl4 = cb4 + (size_t)lvl * KC * D4;

        // stage this level's e2 (read after the chunk-0 barrier below)
        {
            const float4* e2src = (const float4*)(g_e2 + lvl * KC);
            float4 a = e2src[t];
            float4 b = e2src[t + NTHR];
            *(float4*)&e2all[4 * t] = a;
            *(float4*)&e2all[4 * (t + NTHR)] = b;
        }

        float r2r[NR];
#pragma unroll
        for (int i = 0; i < NR; i++) r2r[i] = r2s[rowg + 16 * i];

        float bd[NR]; int bi[NR];
#pragma unroll
        for (int i = 0; i < NR; i++) { bd[i] = 3.4e38f; bi[i] = 0; }

        for (int c = 0; c < NCH; c++) {
            // cs for this chunk was staged earlier; make it visible
            asm volatile("cp.async.wait_group 0;");
            __syncthreads();

            // ---- NRx8 tile, software-pipelined ----
            unsigned long long acc[NR][8];
#pragma unroll
            for (int i = 0; i < NR; i++)
#pragma unroll
                for (int j = 0; j < 8; j++) acc[i][j] = 0ull;

            ulonglong2 rvA[NR], rvB[NR];
#pragma unroll
            for (int i = 0; i < NR; i++) rvA[i] = rvp[528 * i];
            ulonglong2 cvA = cvp[0], cvB;

            // step by 8 q: in-iteration q offsets become immediates
            // (addressing ALU ~2 bumps per 8 steps), body ~16KB fits L1.5 I$
            for (int qq = 0; qq < D4; qq += 8) {
                QSTEP(qq,     rvA, rvB)
                QSTEP(qq + 1, rvB, rvA)
                QSTEP(qq + 2, rvA, rvB)
                QSTEP(qq + 3, rvB, rvA)
                QSTEP(qq + 4, rvA, rvB)
                QSTEP(qq + 5, rvB, rvA)
                QSTEP(qq + 6, rvA, rvB)
                QSTEP(qq + 7, rvB, rvA)
            }

            __syncthreads();   // all warps done reading cs

            // ---- issue next chunk's copy NOW; completes under the epilogue ----
            {
                const float4* nsrc = 0;
                if (c + 1 < NCH)         nsrc = cbl4 + (size_t)(c + 1) * TKC * D4;
                else if (lvl + 1 < MLVL) nsrc = cb4 + (size_t)(lvl + 1) * KC * D4;
                if (nsrc) {
#pragma unroll
                    for (int ii = 0; ii < 16; ii++) {
                        int e = t + NTHR * ii;
                        int k = e >> 5, qq2 = e & 31;
                        cp_async16(&cs[k * RST + 4 * qq2], nsrc + e);
                    }
                    asm volatile("cp.async.commit_group;");
                }
            }

            // ---- distances + running argmin (ascending k, strict <) ----
#pragma unroll
            for (int j = 0; j < 8; j++) {
                int kk = txc + 8 * j;
                float e2k = e2all[c * TKC + kk];
                int kg = c * TKC + kk;
#pragma unroll
                for (int i = 0; i < NR; i++) {
                    float lo, hi;
                    unpack2(acc[i][j], lo, hi);
                    float dot = __fadd_rn(lo, hi);
                    float s = __fadd_rn(r2r[i], e2k);
                    float dv = __fmaf_rn(-2.0f, dot, s);
                    if (dv < bd[i]) { bd[i] = dv; bi[i] = kg; }
                }
            }
        }

        // ---- argmin across the 8 txc lanes (first-min via index tiebreak) ----
#pragma unroll
        for (int off = 1; off <= 4; off <<= 1)
#pragma unroll
            for (int i = 0; i < NR; i++) {
                float od = __shfl_xor_sync(0xffffffffu, bd[i], off);
                int   oi = __shfl_xor_sync(0xffffffffu, bi[i], off);
                if (od < bd[i] || (od == bd[i] && oi < bi[i])) { bd[i] = od; bi[i] = oi; }
            }
        if (txc == 0)
#pragma unroll
            for (int i = 0; i < NR; i++)
                idxs[lvl * TM + rowg + 16 * i] = bi[i];
        __syncthreads();

        // ---- residual update + r2 + loss partial (loss guarded by rowLim) ----
#pragma unroll
        for (int i2 = 0; i2 < TM / 4; i2++) {
            int row = w + 4 * i2;
            int qi = idxs[lvl * TM + row];
            float4 qv = cbl4[(size_t)qi * D4 + l];
            float* rp = &rs[row * RST + 4 * l];
            float4 rv = *(float4*)rp;
            rv.x = __fsub_rn(rv.x, qv.x);
            rv.y = __fsub_rn(rv.y, qv.y);
            rv.z = __fsub_rn(rv.z, qv.z);
            rv.w = __fsub_rn(rv.w, qv.w);
            *(float4*)rp = rv;
            float p = __fmaf_rn(rv.x, rv.x, 0.f);
            p = __fmaf_rn(rv.y, rv.y, p);
            p = __fmaf_rn(rv.z, rv.z, p);
            p = __fmaf_rn(rv.w, rv.w, p);
            if (row < rowLim) lsum += (double)p;   // (q - r_pre)^2 == r_post^2
#pragma unroll
            for (int off = 16; off >= 1; off >>= 1)
                p = __fadd_rn(p, __shfl_xor_sync(0xffffffffu, p, off));
            if (l == 0) r2s[row] = p;
        }
        __syncthreads();
    }

    // ---- y = x + (q_sum - x), reference rounding chain (guarded) ----
    {
        float4* y4 = (float4*)(y + (size_t)rowBase * D);
#pragma unroll
        for (int i2 = 0; i2 < TM / 4; i2++) {
            int row = w + 4 * i2;
            if (row < rowLim) {
                int a0 = idxs[0 * TM + row], a1 = idxs[1 * TM + row];
                int a2 = idxs[2 * TM + row], a3 = idxs[3 * TM + row];
                float4 q0 = cb4[((size_t)0 * KC + a0) * D4 + l];
                float4 q1 = cb4[((size_t)1 * KC + a1) * D4 + l];
                float4 q2 = cb4[((size_t)2 * KC + a2) * D4 + l];
                float4 q3 = cb4[((size_t)3 * KC + a3) * D4 + l];
                float4 xv = x4[(size_t)row * D4 + l];
                float4 o;
                o.x = __fadd_rn(xv.x, __fsub_rn(__fadd_rn(__fadd_rn(__fadd_rn(q0.x, q1.x), q2.x), q3.x), xv.x));
                o.y = __fadd_rn(xv.y, __fsub_rn(__fadd_rn(__fadd_rn(__fadd_rn(q0.y, q1.y), q2.y), q3.y), xv.y));
                o.z = __fadd_rn(xv.z, __fsub_rn(__fadd_rn(__fadd_rn(__fadd_rn(q0.z, q1.z), q2.z), q3.z), xv.z));
                o.w = __fadd_rn(xv.w, __fsub_rn(__fadd_rn(__fadd_rn(__fadd_rn(q0.w, q1.w), q2.w), q3.w), xv.w));
                y4[(size_t)row * D4 + l] = o;
            }
        }
    }

    // ---- deterministic fixed-point loss reduction (int64, replay-safe) ----
    {
        long long lv = (long long)(lsum * LSCALE);
#pragma unroll
        for (int off = 16; off >= 1; off >>= 1)
            lv += __shfl_xor_sync(0xffffffffu, lv, off);
        if (l == 0) atomicAdd(&g_lsum, (unsigned long long)lv);
        __syncthreads();
        if (t == 0) {
            __threadfence();
            unsigned int prev = atomicAdd(&g_count, 1u);
            if (prev == gridDim.x - 1) {
                unsigned long long s = atomicExch(&g_lsum, 0ULL);
                loss_out[0] = (float)(1.25 * ((double)(long long)s / LSCALE)
                                           / (double)nelems);
                atomicExch(&g_count, 0u);
            }
        }
    }
}

extern "C" void kernel_launch(void* const* d_in, const int* in_sizes, int n_in,
                              void* d_out, int out_size) {
    const float* x  = (const float*)d_in[0];
    const float* cb = (const float*)d_in[1];
    float* y = (float*)d_out;

    const long long xelems = (long long)in_sizes[0];
    const int nrows   = (int)(xelems / D);
    const int nblocks = (nrows + TM - 1) / TM;
    float* loss_out = y + xelems;

    cudaFuncSetAttribute(rvq_kernel, cudaFuncAttributeMaxDynamicSharedMemorySize, SMEM_BYTES);

    e2_kernel<<<MLVL * KC / 4, 128>>>(cb);
    rvq_kernel<<<nblocks, NTHR, SMEM_BYTES>>>(x, cb, y, loss_out, nrows, xelems);
}

// round 17
// speedup vs baseline: 2.2126x; 1.0524x over previous
#include <cuda_runtime.h>
#include <cuda_bf16.h>
#include <cstdint>

#define D      128
#define D4     32
#define KC     1024
#define MLVL   4
#define TM     112
#define NTHR   128
#define NCODE  16
#define NCHK   (KC / NCODE)   // 64

#define LSCALE 17179869184.0  // 2^34

__device__ float              g_e2[MLVL * KC];
__device__ __nv_bfloat16      g_split[3][MLVL * KC * D];
__device__ unsigned long long g_lsum  = 0ULL;
__device__ unsigned int       g_count = 0u;

// ---- smem byte layout ----
#define SM_RPLANE 28672                 // 112 rows * 256B
#define SM_R(p)   ((p) * SM_RPLANE)     // residual planes h,m,l
#define SM_B      86016                 // 2 bufs * 3 planes * 16*256
#define SM_BBUF   12288
#define SM_BPL    4096
#define SM_R2     (SM_B + 24576)        // 112 floats
#define SM_IDX    (SM_R2 + 448)         // 4*112 ints
#define SMEM_BYTES (SM_IDX + 1792)      // 112832 -> occ 2

__device__ __forceinline__ void mma_bf16(float* c, const uint32_t* a, const uint32_t* b) {
    asm volatile("mma.sync.aligned.m16n8k16.row.col.f32.bf16.bf16.f32 "
        "{%0,%1,%2,%3}, {%4,%5,%6,%7}, {%8,%9}, {%0,%1,%2,%3};"
        : "+f"(c[0]), "+f"(c[1]), "+f"(c[2]), "+f"(c[3])
        : "r"(a[0]), "r"(a[1]), "r"(a[2]), "r"(a[3]), "r"(b[0]), "r"(b[1]));
}
__device__ __forceinline__ void ldsm_x4(uint32_t* r, uint32_t a) {
    asm volatile("ldmatrix.sync.aligned.m8n8.x4.shared.b16 {%0,%1,%2,%3}, [%4];"
        : "=r"(r[0]), "=r"(r[1]), "=r"(r[2]), "=r"(r[3]) : "r"(a));
}
__device__ __forceinline__ void ldsm_x2(uint32_t* r, uint32_t a) {
    asm volatile("ldmatrix.sync.aligned.m8n8.x2.shared.b16 {%0,%1}, [%2];"
        : "=r"(r[0]), "=r"(r[1]) : "r"(a));
}
__device__ __forceinline__ void cp_async16(uint32_t saddr, const void* g) {
    asm volatile("cp.async.ca.shared.global [%0], [%1], 16;" :: "r"(saddr), "l"(g));
}
__device__ __forceinline__ void split3(float v, unsigned short& hb,
                                       unsigned short& mb, unsigned short& lb) {
    __nv_bfloat16 h = __float2bfloat16(v);
    float r1 = __fsub_rn(v, __bfloat162float(h));
    __nv_bfloat16 m = __float2bfloat16(r1);
    float r2 = __fsub_rn(r1, __bfloat162float(m));
    __nv_bfloat16 lo = __float2bfloat16(r2);
    hb = __bfloat16_as_ushort(h);
    mb = __bfloat16_as_ushort(m);
    lb = __bfloat16_as_ushort(lo);
}
__device__ __forceinline__ float bf2f(unsigned short u) {
    return __bfloat162float(__ushort_as_bfloat16(u));
}

// ---- e2[k] = sum_d cb[k][d]^2 ----
__global__ void e2_kernel(const float* __restrict__ cb) {
    int code = blockIdx.x * 4 + (threadIdx.x >> 5);
    int l = threadIdx.x & 31;
    const float4* row = (const float4*)(cb + (size_t)code * D);
    float4 v = row[l];
    float p = __fmaf_rn(v.x, v.x, 0.f);
    p = __fmaf_rn(v.y, v.y, p);
    p = __fmaf_rn(v.z, v.z, p);
    p = __fmaf_rn(v.w, v.w, p);
#pragma unroll
    for (int off = 16; off >= 1; off >>= 1)
        p = __fadd_rn(p, __shfl_xor_sync(0xffffffffu, p, off));
    if (l == 0) g_e2[code] = p;
}

// ---- codebook 3-way bf16 split ----
__global__ void split_cb_kernel(const float* __restrict__ cb) {
    int i = blockIdx.x * blockDim.x + threadIdx.x;
    if (i < MLVL * KC * D) {
        unsigned short hb, mb, lb;
        split3(cb[i], hb, mb, lb);
        g_split[0][i] = __ushort_as_bfloat16(hb);
        g_split[1][i] = __ushort_as_bfloat16(mb);
        g_split[2][i] = __ushort_as_bfloat16(lb);
    }
}

__device__ __forceinline__ void stage_chunk(uint32_t sbase, int lvl, int c, int buf, int t) {
    uint32_t dstb = sbase + SM_B + buf * SM_BBUF;
#pragma unroll
    for (int ii = 0; ii < 6; ii++) {
        int idx = t + NTHR * ii;        // 0..767
        int p = idx >> 8;
        int rem = idx & 255;
        int code = rem >> 4, seg = rem & 15;
        const __nv_bfloat16* src =
            g_split[p] + ((size_t)(lvl * KC + c * NCODE + code) * D + seg * 8);
        uint32_t dst = dstb + p * SM_BPL + code * 256 + ((seg ^ (code & 7)) << 4);
        cp_async16(dst, src);
    }
    asm volatile("cp.async.commit_group;");
}

__global__ __launch_bounds__(NTHR, 2)
void rvq_mma_kernel(const float* __restrict__ x, const float* __restrict__ cb,
                    float* __restrict__ y, float* __restrict__ loss_out,
                    int nrows, long long nelems) {
    extern __shared__ char smem[];
    uint32_t sbase = (uint32_t)__cvta_generic_to_shared(smem);
    float* r2s = (float*)(smem + SM_R2);
    int*   idxs = (int*)(smem + SM_IDX);

    const int t = threadIdx.x, w = t >> 5, l = t & 31;
    const int rowBase = blockIdx.x * TM;
    if (rowBase >= nrows) return;
    const int rowLim = (nrows - rowBase < TM) ? (nrows - rowBase) : TM;
    const float4* x4  = (const float4*)(x + (size_t)rowBase * D);
    const float4* cb4 = (const float4*)cb;

    const int ntile = (w < 2) ? 4 : 3;
    const int tbase = (w < 2) ? 4 * w : 8 + 3 * (w - 2);

    double lsum = 0.0;

    stage_chunk(sbase, 0, 0, 0, t);   // lvl0 chunk0 overlaps init

    // ---- init: x -> 3 bf16 planes (exact split) + r2 ----
#pragma unroll
    for (int i2 = 0; i2 < TM / 4; i2++) {
        int row = w + 4 * i2;
        float4 v = make_float4(0.f, 0.f, 0.f, 0.f);
        if (row < rowLim) v = x4[(size_t)row * D4 + l];
        float e[4] = {v.x, v.y, v.z, v.w};
        unsigned short hb[4], mb[4], lb[4];
#pragma unroll
        for (int u = 0; u < 4; u++) split3(e[u], hb[u], mb[u], lb[u]);
        uint32_t a = sbase + row * 256 + ((((l >> 1) ^ (row & 7)) & 15) << 4) + (l & 1) * 8;
        uint32_t p0 = (uint32_t)hb[0] | ((uint32_t)hb[1] << 16), p1 = (uint32_t)hb[2] | ((uint32_t)hb[3] << 16);
        asm volatile("st.shared.v2.b32 [%0], {%1,%2};" :: "r"(a + SM_R(0)), "r"(p0), "r"(p1));
        p0 = (uint32_t)mb[0] | ((uint32_t)mb[1] << 16); p1 = (uint32_t)mb[2] | ((uint32_t)mb[3] << 16);
        asm volatile("st.shared.v2.b32 [%0], {%1,%2};" :: "r"(a + SM_R(1)), "r"(p0), "r"(p1));
        p0 = (uint32_t)lb[0] | ((uint32_t)lb[1] << 16); p1 = (uint32_t)lb[2] | ((uint32_t)lb[3] << 16);
        asm volatile("st.shared.v2.b32 [%0], {%1,%2};" :: "r"(a + SM_R(2)), "r"(p0), "r"(p1));
        float p = __fmaf_rn(v.x, v.x, 0.f);
        p = __fmaf_rn(v.y, v.y, p);
        p = __fmaf_rn(v.z, v.z, p);
        p = __fmaf_rn(v.w, v.w, p);
#pragma unroll
        for (int off = 16; off >= 1; off >>= 1)
            p = __fadd_rn(p, __shfl_xor_sync(0xffffffffu, p, off));
        if (l == 0) r2s[row] = p;
    }
    __syncthreads();

    // per-thread ldmatrix address components
    const int arow = l & 15, akh = l >> 4;                 // A: codebook chunk
    const int brow1 = (tbase + (l >> 4)) * 8 + (l & 7);    // B pair1: tiles 0,1
    const int bkh1  = (l >> 3) & 1;
    const int brow2 = (tbase + 2 + (l >> 4)) * 8 + (l & 7);// B pair2: tiles 2,3
    const int brow3 = (tbase + 2) * 8 + (l & 7);           // B x2: tile 2 (3-tile warps)

    for (int lvl = 0; lvl < MLVL; lvl++) {
        const float4* cbl4 = cb4 + (size_t)lvl * KC * D4;
        if (lvl > 0) stage_chunk(sbase, lvl, 0, 0, t);

        float r2c[4][2];
#pragma unroll
        for (int tt = 0; tt < 4; tt++)
#pragma unroll
            for (int j = 0; j < 2; j++)
                r2c[tt][j] = (tt < ntile) ? r2s[(tbase + tt) * 8 + (l & 3) * 2 + j] : 0.f;

        float bd[4][2]; int bi[4][2];
#pragma unroll
        for (int tt = 0; tt < 4; tt++)
#pragma unroll
            for (int j = 0; j < 2; j++) { bd[tt][j] = 3.4e38f; bi[tt][j] = 0; }

        for (int c = 0; c < NCHK; c++) {
            if (c + 1 < NCHK) stage_chunk(sbase, lvl, c + 1, (c + 1) & 1, t);
            if (c + 1 < NCHK) asm volatile("cp.async.wait_group 1;" ::: "memory");
            else              asm volatile("cp.async.wait_group 0;" ::: "memory");
            __syncthreads();

            const uint32_t bb = sbase + SM_B + (c & 1) * SM_BBUF;
            float a0[4][4], a1[4][4];
#pragma unroll
            for (int tt = 0; tt < 4; tt++)
#pragma unroll
                for (int e = 0; e < 4; e++) { a0[tt][e] = 0.f; a1[tt][e] = 0.f; }

#pragma unroll
            for (int ks = 0; ks < 8; ks++) {
                uint32_t ah[4], am[4], al_[4];
                {
                    uint32_t aa = bb + arow * 256 + (((2 * ks + akh) ^ (arow & 7)) << 4);
                    ldsm_x4(ah, aa);
                    ldsm_x4(am, aa + SM_BPL);
                    ldsm_x4(al_, aa + 2 * SM_BPL);
                }
                uint32_t rbh[4][2], rbm[4][2], rbl[4][2];
                {
                    uint32_t b1 = sbase + brow1 * 256 + (((2 * ks + bkh1) ^ (brow1 & 7)) << 4);
                    uint32_t q[4];
                    ldsm_x4(q, b1 + SM_R(0));
                    rbh[0][0]=q[0]; rbh[0][1]=q[1]; rbh[1][0]=q[2]; rbh[1][1]=q[3];
                    ldsm_x4(q, b1 + SM_R(1));
                    rbm[0][0]=q[0]; rbm[0][1]=q[1]; rbm[1][0]=q[2]; rbm[1][1]=q[3];
                    ldsm_x4(q, b1 + SM_R(2));
                    rbl[0][0]=q[0]; rbl[0][1]=q[1]; rbl[1][0]=q[2]; rbl[1][1]=q[3];
                    if (ntile == 4) {
                        uint32_t b2 = sbase + brow2 * 256 + (((2 * ks + bkh1) ^ (brow2 & 7)) << 4);
                        ldsm_x4(q, b2 + SM_R(0));
                        rbh[2][0]=q[0]; rbh[2][1]=q[1]; rbh[3][0]=q[2]; rbh[3][1]=q[3];
                        ldsm_x4(q, b2 + SM_R(1));
                        rbm[2][0]=q[0]; rbm[2][1]=q[1]; rbm[3][0]=q[2]; rbm[3][1]=q[3];
                        ldsm_x4(q, b2 + SM_R(2));
                        rbl[2][0]=q[0]; rbl[2][1]=q[1]; rbl[3][0]=q[2]; rbl[3][1]=q[3];
                    } else {
                        uint32_t b3 = sbase + brow3 * 256 + (((2 * ks + bkh1) ^ (brow3 & 7)) << 4);
                        uint32_t q2[2];
                        ldsm_x2(q2, b3 + SM_R(0)); rbh[2][0]=q2[0]; rbh[2][1]=q2[1];
                        ldsm_x2(q2, b3 + SM_R(1)); rbm[2][0]=q2[0]; rbm[2][1]=q2[1];
                        ldsm_x2(q2, b3 + SM_R(2)); rbl[2][0]=q2[0]; rbl[2][1]=q2[1];
                        rbh[3][0]=rbh[3][1]=rbm[3][0]=rbm[3][1]=rbl[3][0]=rbl[3][1]=0u;
                    }
                }
#pragma unroll
                for (int tt = 0; tt < 4; tt++) {
                    if (tt < ntile) {
                        mma_bf16(a0[tt], ah, rbh[tt]);   // h*h
                        mma_bf16(a1[tt], ah, rbm[tt]);   // h(cb)*m(res)
                        mma_bf16(a0[tt], am, rbm[tt]);   // m*m
                        mma_bf16(a1[tt], am, rbh[tt]);   // m(cb)*h(res)
                        mma_bf16(a0[tt], ah, rbl[tt]);   // h(cb)*l(res)
                        mma_bf16(a1[tt], al_, rbh[tt]);  // l(cb)*h(res)
                    }
                }
            }
            __syncthreads();   // all warps done reading bufs before next overwrite

            // ---- dist + running argmin (codes ascending, strict <) ----
            const int cb0 = c * NCODE + (l >> 2);
            const int cb1 = cb0 + 8;
            const float e20 = g_e2[lvl * KC + cb0];
            const float e21 = g_e2[lvl * KC + cb1];
#pragma unroll
            for (int tt = 0; tt < 4; tt++) {
                if (tt < ntile) {
#pragma unroll
                    for (int j = 0; j < 2; j++) {
                        float dot0 = __fadd_rn(a0[tt][j],     a1[tt][j]);
                        float dot1 = __fadd_rn(a0[tt][2 + j], a1[tt][2 + j]);
                        float s0 = __fadd_rn(r2c[tt][j], e20);
                        float d0 = __fmaf_rn(-2.0f, dot0, s0);
                        if (d0 < bd[tt][j]) { bd[tt][j] = d0; bi[tt][j] = cb0; }
                        float s1 = __fadd_rn(r2c[tt][j], e21);
                        float d1 = __fmaf_rn(-2.0f, dot1, s1);
                        if (d1 < bd[tt][j]) { bd[tt][j] = d1; bi[tt][j] = cb1; }
                    }
                }
            }
        }

        // ---- argmin across the 8 lanes sharing each row (xor 4,8,16) ----
#pragma unroll
        for (int off = 4; off <= 16; off <<= 1)
#pragma unroll
            for (int tt = 0; tt < 4; tt++)
#pragma unroll
                for (int j = 0; j < 2; j++) {
                    float od = __shfl_xor_sync(0xffffffffu, bd[tt][j], off);
                    int   oi = __shfl_xor_sync(0xffffffffu, bi[tt][j], off);
                    if (od < bd[tt][j] || (od == bd[tt][j] && oi < bi[tt][j])) {
                        bd[tt][j] = od; bi[tt][j] = oi;
                    }
                }
        if ((l >> 2) == 0)
#pragma unroll
            for (int tt = 0; tt < 4; tt++)
                if (tt < ntile)
#pragma unroll
                    for (int j = 0; j < 2; j++)
                        idxs[lvl * TM + (tbase + tt) * 8 + l * 2 + j] = bi[tt][j];
        __syncthreads();

        // ---- residual update: reconstruct exact fp32, sub q, re-split ----
#pragma unroll
        for (int i2 = 0; i2 < TM / 4; i2++) {
            int row = w + 4 * i2;
            int qi = idxs[lvl * TM + row];
            float4 qv = cbl4[(size_t)qi * D4 + l];
            uint32_t a = sbase + row * 256 + ((((l >> 1) ^ (row & 7)) & 15) << 4) + (l & 1) * 8;
            uint32_t h0, h1, m0, m1, l0, l1;
            asm volatile("ld.shared.v2.b32 {%0,%1}, [%2];" : "=r"(h0), "=r"(h1) : "r"(a + SM_R(0)));
            asm volatile("ld.shared.v2.b32 {%0,%1}, [%2];" : "=r"(m0), "=r"(m1) : "r"(a + SM_R(1)));
            asm volatile("ld.shared.v2.b32 {%0,%1}, [%2];" : "=r"(l0), "=r"(l1) : "r"(a + SM_R(2)));
            float r[4], q[4] = {qv.x, qv.y, qv.z, qv.w};
            r[0] = __fadd_rn(__fadd_rn(bf2f(h0 & 0xffff), bf2f(m0 & 0xffff)), bf2f(l0 & 0xffff));
            r[1] = __fadd_rn(__fadd_rn(bf2f(h0 >> 16),    bf2f(m0 >> 16)),    bf2f(l0 >> 16));
            r[2] = __fadd_rn(__fadd_rn(bf2f(h1 & 0xffff), bf2f(m1 & 0xffff)), bf2f(l1 & 0xffff));
            r[3] = __fadd_rn(__fadd_rn(bf2f(h1 >> 16),    bf2f(m1 >> 16)),    bf2f(l1 >> 16));
            float p = 0.f;
            unsigned short hb[4], mb[4], lb[4];
#pragma unroll
            for (int u = 0; u < 4; u++) {
                r[u] = __fsub_rn(r[u], q[u]);
                p = __fmaf_rn(r[u], r[u], p);
                split3(r[u], hb[u], mb[u], lb[u]);
            }
            uint32_t p0 = (uint32_t)hb[0] | ((uint32_t)hb[1] << 16), p1 = (uint32_t)hb[2] | ((uint32_t)hb[3] << 16);
            asm volatile("st.shared.v2.b32 [%0], {%1,%2};" :: "r"(a + SM_R(0)), "r"(p0), "r"(p1));
            p0 = (uint32_t)mb[0] | ((uint32_t)mb[1] << 16); p1 = (uint32_t)mb[2] | ((uint32_t)mb[3] << 16);
            asm volatile("st.shared.v2.b32 [%0], {%1,%2};" :: "r"(a + SM_R(1)), "r"(p0), "r"(p1));
            p0 = (uint32_t)lb[0] | ((uint32_t)lb[1] << 16); p1 = (uint32_t)lb[2] | ((uint32_t)lb[3] << 16);
            asm volatile("st.shared.v2.b32 [%0], {%1,%2};" :: "r"(a + SM_R(2)), "r"(p0), "r"(p1));
            if (row < rowLim) lsum += (double)p;
#pragma unroll
            for (int off = 16; off >= 1; off >>= 1)
                p = __fadd_rn(p, __shfl_xor_sync(0xffffffffu, p, off));
            if (l == 0) r2s[row] = p;
        }
        __syncthreads();
    }

    // ---- y = x + (q_sum - x), reference rounding chain ----
    {
        float4* y4 = (float4*)(y + (size_t)rowBase * D);
#pragma unroll
        for (int i2 = 0; i2 < TM / 4; i2++) {
            int row = w + 4 * i2;
            if (row < rowLim) {
                int a0i = idxs[0 * TM + row], a1i = idxs[1 * TM + row];
                int a2i = idxs[2 * TM + row], a3i = idxs[3 * TM + row];
                float4 q0 = cb4[((size_t)0 * KC + a0i) * D4 + l];
                float4 q1 = cb4[((size_t)1 * KC + a1i) * D4 + l];
                float4 q2 = cb4[((size_t)2 * KC + a2i) * D4 + l];
                float4 q3 = cb4[((size_t)3 * KC + a3i) * D4 + l];
                float4 xv = x4[(size_t)row * D4 + l];
                float4 o;
                o.x = __fadd_rn(xv.x, __fsub_rn(__fadd_rn(__fadd_rn(__fadd_rn(q0.x, q1.x), q2.x), q3.x), xv.x));
                o.y = __fadd_rn(xv.y, __fsub_rn(__fadd_rn(__fadd_rn(__fadd_rn(q0.y, q1.y), q2.y), q3.y), xv.y));
                o.z = __fadd_rn(xv.z, __fsub_rn(__fadd_rn(__fadd_rn(__fadd_rn(q0.z, q1.z), q2.z), q3.z), xv.z));
                o.w = __fadd_rn(xv.w, __fsub_rn(__fadd_rn(__fadd_rn(__fadd_rn(q0.w, q1.w), q2.w), q3.w), xv.w));
                y4[(size_t)row * D4 + l] = o;
            }
        }
    }

    // ---- deterministic fixed-point loss reduction (replay-safe) ----
    {
        long long lv = (long long)(lsum * LSCALE);
#pragma unroll
        for (int off = 16; off >= 1; off >>= 1)
            lv += __shfl_xor_sync(0xffffffffu, lv, off);
        if (l == 0) atomicAdd(&g_lsum, (unsigned long long)lv);
        __syncthreads();
        if (t == 0) {
            __threadfence();
            unsigned int prev = atomicAdd(&g_count, 1u);
            if (prev == gridDim.x - 1) {
                unsigned long long s = atomicExch(&g_lsum, 0ULL);
                loss_out[0] = (float)(1.25 * ((double)(long long)s / LSCALE)
                                           / (double)nelems);
                atomicExch(&g_count, 0u);
            }
        }
    }
}

extern "C" void kernel_launch(void* const* d_in, const int* in_sizes, int n_in,
                              void* d_out, int out_size) {
    const float* x  = (const float*)d_in[0];
    const float* cb = (const float*)d_in[1];
    float* y = (float*)d_out;

    const long long xelems = (long long)in_sizes[0];
    const int nrows   = (int)(xelems / D);
    const int nblocks = (nrows + TM - 1) / TM;
    float* loss_out = y + xelems;

    cudaFuncSetAttribute(rvq_mma_kernel, cudaFuncAttributeMaxDynamicSharedMemorySize, SMEM_BYTES);

    e2_kernel<<<MLVL * KC / 4, 128>>>(cb);
    split_cb_kernel<<<(MLVL * KC * D + 255) / 256, 256>>>(cb);
    rvq_mma_kernel<<<nblocks, NTHR, SMEM_BYTES>>>(x, cb, y, loss_out, nrows, xelems);
}